// round 1
// baseline (speedup 1.0000x reference)
#include <cuda_runtime.h>
#include <math.h>

// Problem constants
#define SQ   2048
#define DM   1024
#define NH   16
#define HDIM 64
#define MLPD 4096
#define NL   4
#define HALFW 256
#define NG   64

// Scratch (device globals; no allocation allowed)
__device__ float g_x[SQ * DM];
__device__ float g_h[SQ * DM];
__device__ float g_q[SQ * DM];
__device__ float g_k[SQ * DM];
__device__ float g_v[SQ * DM];
__device__ float g_ctx[SQ * DM];
__device__ float g_y1[SQ * MLPD];

// ---------------------------------------------------------------------------
// Embedding + sinusoidal positional encoding
// ---------------------------------------------------------------------------
__global__ void embed_kernel(const int* __restrict__ inputs,
                             const float* __restrict__ emb) {
    int idx = blockIdx.x * blockDim.x + threadIdx.x;  // over SQ*DM
    int s = idx >> 10;
    int d = idx & 1023;
    int tok = inputs[s];
    float val = emb[tok * DM + d];
    int k2 = d >> 1;
    // div = exp((2k) * (-ln(10000)/D))
    float div = expf((float)(2 * k2) * (-9.210340371976184f / 1024.0f));
    float ang = (float)s * div;
    val += (d & 1) ? cosf(ang) : sinf(ang);
    g_x[idx] = val;
}

// ---------------------------------------------------------------------------
// LayerNorm: one block (256 threads) per row of 1024
// ---------------------------------------------------------------------------
__device__ __forceinline__ float block_reduce_sum(float v) {
    __shared__ float sm[8];
    int lane = threadIdx.x & 31;
    int warp = threadIdx.x >> 5;
#pragma unroll
    for (int o = 16; o; o >>= 1) v += __shfl_xor_sync(0xffffffffu, v, o);
    if (lane == 0) sm[warp] = v;
    __syncthreads();
    if (warp == 0) {
        v = (lane < 8) ? sm[lane] : 0.0f;
#pragma unroll
        for (int o = 4; o; o >>= 1) v += __shfl_xor_sync(0xffffffffu, v, o);
        if (lane == 0) sm[0] = v;
    }
    __syncthreads();
    float r = sm[0];
    __syncthreads();
    return r;
}

__global__ void ln_kernel(const float* __restrict__ in,
                          const float* __restrict__ scale,
                          const float* __restrict__ bias,
                          float* __restrict__ out) {
    int row = blockIdx.x;
    float4 v = ((const float4*)(in + row * DM))[threadIdx.x];
    float mu = block_reduce_sum(v.x + v.y + v.z + v.w) * (1.0f / DM);
    float dx = v.x - mu, dy = v.y - mu, dz = v.z - mu, dw = v.w - mu;
    float var = block_reduce_sum(dx * dx + dy * dy + dz * dz + dw * dw) * (1.0f / DM);
    float rs = rsqrtf(var + 1e-6f);
    float4 s4 = ((const float4*)scale)[threadIdx.x];
    float4 b4 = ((const float4*)bias)[threadIdx.x];
    float4 o;
    o.x = dx * rs * s4.x + b4.x;
    o.y = dy * rs * s4.y + b4.y;
    o.z = dz * rs * s4.z + b4.z;
    o.w = dw * rs * s4.w + b4.w;
    ((float4*)(out + row * DM))[threadIdx.x] = o;
}

// ---------------------------------------------------------------------------
// SGEMM: C[M,N] = epilogue(alpha * A[M,K] @ B[K,N])
// 128x128 block tile, BK=8, 256 threads, 8x8 per thread.
// All dims are multiples of tile sizes for this problem -> no bounds checks.
// ---------------------------------------------------------------------------
template <int BIAS, int RELU, int RESID>
__global__ __launch_bounds__(256) void sgemm_kernel(
    const float* __restrict__ A, const float* __restrict__ B,
    const float* __restrict__ bias, const float* __restrict__ resid,
    float* __restrict__ C, int M, int N, int K, float alpha) {
    const int BM = 128, BN = 128, BK = 8;
    __shared__ float As[BK][BM];
    __shared__ float Bs[BK][BN];
    int tid = threadIdx.x;
    int tx = tid & 15, ty = tid >> 4;
    const float* Ab = A + (size_t)blockIdx.y * BM * K;
    const float* Bb = B + (size_t)blockIdx.x * BN;
    int aRow = tid >> 1, aCol = (tid & 1) << 2;
    int bRow = tid >> 5, bCol = (tid & 31) << 2;
    float acc[8][8] = {};
    for (int k0 = 0; k0 < K; k0 += BK) {
        float4 a4 = *(const float4*)(Ab + (size_t)aRow * K + k0 + aCol);
        As[aCol + 0][aRow] = a4.x;
        As[aCol + 1][aRow] = a4.y;
        As[aCol + 2][aRow] = a4.z;
        As[aCol + 3][aRow] = a4.w;
        *(float4*)(&Bs[bRow][bCol]) =
            *(const float4*)(Bb + (size_t)(k0 + bRow) * N + bCol);
        __syncthreads();
#pragma unroll
        for (int kk = 0; kk < BK; kk++) {
            float ar[8], br[8];
            *(float4*)(ar) = *(float4*)(&As[kk][ty * 8]);
            *(float4*)(ar + 4) = *(float4*)(&As[kk][ty * 8 + 4]);
            *(float4*)(br) = *(float4*)(&Bs[kk][tx * 8]);
            *(float4*)(br + 4) = *(float4*)(&Bs[kk][tx * 8 + 4]);
#pragma unroll
            for (int i = 0; i < 8; i++)
#pragma unroll
                for (int j = 0; j < 8; j++) acc[i][j] += ar[i] * br[j];
        }
        __syncthreads();
    }
    int row0 = blockIdx.y * BM + ty * 8;
    int col0 = blockIdx.x * BN + tx * 8;
#pragma unroll
    for (int i = 0; i < 8; i++) {
        int row = row0 + i;
#pragma unroll
        for (int j = 0; j < 8; j++) {
            int col = col0 + j;
            float v = acc[i][j] * alpha;
            if (BIAS) v += bias[col];
            if (RELU) v = fmaxf(v, 0.0f);
            if (RESID) v += resid[(size_t)row * N + col];
            C[(size_t)row * N + col] = v;
        }
    }
}

// ---------------------------------------------------------------------------
// Sparse attention: one block (128 thr) per (query row, head).
// Allowed keys for row i: all j if i < NG; else [0,NG) U [max(NG,i-HALFW), min(S,i+HALFW+1))
// Two-pass softmax with compact score buffer in smem.
// ---------------------------------------------------------------------------
__global__ __launch_bounds__(128) void attn_kernel() {
    int i = blockIdx.x;
    int head = blockIdx.y;
    __shared__ float qs[HDIM];
    __shared__ float sc[SQ];
    __shared__ float red[128];
    int tid = threadIdx.x;

    if (tid < HDIM) qs[tid] = g_q[(size_t)i * DM + head * HDIM + tid];
    __syncthreads();

    int n0, r1lo, r1hi;
    if (i < NG) {
        n0 = SQ; r1lo = 0; r1hi = 0;
    } else {
        n0 = NG;
        r1lo = max(NG, i - HALFW);
        r1hi = min(SQ, i + HALFW + 1);
    }
    int n = n0 + (r1hi - r1lo);

    // Pass 1: scores. One warp per key, lanes split the 64-dim dot.
    int warp = tid >> 5, lane = tid & 31;
    for (int t = warp; t < n; t += 4) {
        int j = (t < n0) ? t : (r1lo + (t - n0));
        const float* kr = g_k + (size_t)j * DM + head * HDIM;
        float2 kk = ((const float2*)kr)[lane];
        float p = qs[2 * lane] * kk.x + qs[2 * lane + 1] * kk.y;
#pragma unroll
        for (int o = 16; o; o >>= 1) p += __shfl_xor_sync(0xffffffffu, p, o);
        if (lane == 0) sc[t] = p;
    }
    __syncthreads();

    // Row max
    float m = -1e30f;
    for (int t = tid; t < n; t += 128) m = fmaxf(m, sc[t]);
    red[tid] = m;
    __syncthreads();
    for (int s2 = 64; s2 > 0; s2 >>= 1) {
        if (tid < s2) red[tid] = fmaxf(red[tid], red[tid + s2]);
        __syncthreads();
    }
    m = red[0];
    __syncthreads();

    // exp + sum
    float lsum = 0.0f;
    for (int t = tid; t < n; t += 128) {
        float e = expf(sc[t] - m);
        sc[t] = e;
        lsum += e;
    }
    red[tid] = lsum;
    __syncthreads();
    for (int s2 = 64; s2 > 0; s2 >>= 1) {
        if (tid < s2) red[tid] += red[tid + s2];
        __syncthreads();
    }
    float denom = red[0];
    __syncthreads();

    // Pass 3: P @ V. Threads 0-63 handle even t, 64-127 odd t, dim = tid&63.
    int g = tid >> 6;
    int d = tid & 63;
    float acc = 0.0f;
    for (int t = g; t < n; t += 2) {
        int j = (t < n0) ? t : (r1lo + (t - n0));
        acc += sc[t] * g_v[(size_t)j * DM + head * HDIM + d];
    }
    red[tid] = acc;
    __syncthreads();
    if (tid < 64)
        g_ctx[(size_t)i * DM + head * HDIM + tid] = (red[tid] + red[64 + tid]) / denom;
}

// ---------------------------------------------------------------------------
// Launch
// ---------------------------------------------------------------------------
extern "C" void kernel_launch(void* const* d_in, const int* in_sizes, int n_in,
                              void* d_out, int out_size) {
    const int* inputs = (const int*)d_in[0];
    // d_in[1] = global_mask: deterministic constant (first NG tokens) -> folded in
    const float* embed = (const float*)d_in[2];
    const float* wq = (const float*)d_in[3];
    const float* wk = (const float*)d_in[4];
    const float* wv = (const float*)d_in[5];
    const float* wo = (const float*)d_in[6];
    const float* ln1s = (const float*)d_in[7];
    const float* ln1b = (const float*)d_in[8];
    const float* ln2s = (const float*)d_in[9];
    const float* ln2b = (const float*)d_in[10];
    const float* w1 = (const float*)d_in[11];
    const float* b1 = (const float*)d_in[12];
    const float* w2 = (const float*)d_in[13];
    const float* b2 = (const float*)d_in[14];
    const float* lnfs = (const float*)d_in[15];
    const float* lnfb = (const float*)d_in[16];
    float* out = (float*)d_out;

    float *xp, *hp, *qp, *kp, *vp, *cp, *yp;
    cudaGetSymbolAddress((void**)&xp, g_x);
    cudaGetSymbolAddress((void**)&hp, g_h);
    cudaGetSymbolAddress((void**)&qp, g_q);
    cudaGetSymbolAddress((void**)&kp, g_k);
    cudaGetSymbolAddress((void**)&vp, g_v);
    cudaGetSymbolAddress((void**)&cp, g_ctx);
    cudaGetSymbolAddress((void**)&yp, g_y1);

    embed_kernel<<<SQ * DM / 256, 256>>>(inputs, embed);

    const size_t W_ATT = (size_t)DM * NH * HDIM;   // 1M per layer
    const size_t W_MLP = (size_t)DM * MLPD;        // 4M per layer
    dim3 g_1024(DM / 128, SQ / 128);               // (8,16)
    dim3 g_4096(MLPD / 128, SQ / 128);             // (32,16)

    for (int l = 0; l < NL; l++) {
        ln_kernel<<<SQ, 256>>>(xp, ln1s + l * DM, ln1b + l * DM, hp);

        sgemm_kernel<0, 0, 0><<<g_1024, 256>>>(hp, wq + l * W_ATT, nullptr, nullptr,
                                               qp, SQ, DM, DM, 0.125f);
        sgemm_kernel<0, 0, 0><<<g_1024, 256>>>(hp, wk + l * W_ATT, nullptr, nullptr,
                                               kp, SQ, DM, DM, 1.0f);
        sgemm_kernel<0, 0, 0><<<g_1024, 256>>>(hp, wv + l * W_ATT, nullptr, nullptr,
                                               vp, SQ, DM, DM, 1.0f);

        attn_kernel<<<dim3(SQ, NH), 128>>>();

        // x = x + ctx @ wo
        sgemm_kernel<0, 0, 1><<<g_1024, 256>>>(cp, wo + l * W_ATT, nullptr, xp,
                                               xp, SQ, DM, DM, 1.0f);

        ln_kernel<<<SQ, 256>>>(xp, ln2s + l * DM, ln2b + l * DM, hp);

        // y1 = relu(h @ w1 + b1)
        sgemm_kernel<1, 1, 0><<<g_4096, 256>>>(hp, w1 + l * W_MLP, b1 + l * MLPD,
                                               nullptr, yp, SQ, MLPD, DM, 1.0f);
        // x = x + y1 @ w2 + b2
        sgemm_kernel<1, 0, 1><<<g_1024, 256>>>(yp, w2 + l * W_MLP, b2 + l * DM, xp,
                                               xp, SQ, DM, MLPD, 1.0f);
    }

    ln_kernel<<<SQ, 256>>>(xp, lnfs, lnfb, out);
}

// round 3
// speedup vs baseline: 1.6354x; 1.6354x over previous
#include <cuda_runtime.h>
#include <cuda_bf16.h>
#include <math.h>
#include <stdint.h>

#define SQ   2048
#define DM   1024
#define NH   16
#define HDIM 64
#define MLPD 4096
#define NL   4
#define HALFW 256
#define NG   64

// ---------------- scratch (device globals; no allocation allowed) ----------
__device__ float g_x[SQ * DM];
__device__ float g_h[SQ * DM];
__device__ float g_q[SQ * DM];
__device__ float g_k[SQ * DM];
__device__ float g_v[SQ * DM];
__device__ float g_ctx[SQ * DM];
__device__ float g_y1[SQ * MLPD];
__device__ float g_wqT[NL * DM * DM];
__device__ float g_wkT[NL * DM * DM];
__device__ float g_wvT[NL * DM * DM];
__device__ float g_woT[NL * DM * DM];
__device__ float g_w1T[NL * DM * MLPD];
__device__ float g_w2T[NL * MLPD * DM];

// ---------------- helpers ---------------------------------------------------
__device__ __forceinline__ uint32_t smem_u32(const void* p) {
    uint32_t a;
    asm("{ .reg .u64 t; cvta.to.shared.u64 t, %1; cvt.u32.u64 %0, t; }"
        : "=r"(a) : "l"(p));
    return a;
}

__device__ __forceinline__ void ldsm4(uint32_t* r, uint32_t addr) {
    asm volatile("ldmatrix.sync.aligned.m8n8.x4.shared.b16 {%0,%1,%2,%3}, [%4];"
                 : "=r"(r[0]), "=r"(r[1]), "=r"(r[2]), "=r"(r[3]) : "r"(addr));
}

__device__ __forceinline__ void mma_bf16(float* c, const uint32_t* a,
                                         const uint32_t* b) {
    asm volatile(
        "mma.sync.aligned.m16n8k16.row.col.f32.bf16.bf16.f32 "
        "{%0,%1,%2,%3}, {%4,%5,%6,%7}, {%8,%9}, {%0,%1,%2,%3};"
        : "+f"(c[0]), "+f"(c[1]), "+f"(c[2]), "+f"(c[3])
        : "r"(a[0]), "r"(a[1]), "r"(a[2]), "r"(a[3]), "r"(b[0]), "r"(b[1]));
}

// smem geometry (bytes)
#define ROWB  80            // 32 bf16 = 64B data + 16B pad (5 x 16B -> conflict-free)
#define PART  (128 * ROWB)  // one operand-part tile: 10240 B
#define BUFB  (4 * PART)    // Ah, Al, Bh, Bl
#define DYNSM (2 * BUFB)    // double buffer: 81920 B

// ---------------------------------------------------------------------------
// bf16-split tensor-core GEMM: C[M,N] = epi(alpha * A[M,K] @ BT[N,K]^T)
// A fp32 [M,K] row-major, BT fp32 [N,K] row-major.
// 128x128x32 tile, 256 thr, warp tile 64x32, m16n8k16 mma.sync,
// 3-term bf16 split (hi*hi + hi*lo + lo*hi).
// ---------------------------------------------------------------------------
template <int BIAS, int RELU, int RESID>
__global__ __launch_bounds__(256) void mma_gemm(
    const float* __restrict__ A, const float* __restrict__ BT,
    const float* __restrict__ bias, const float* __restrict__ resid,
    float* __restrict__ C, int K, int N, float alpha) {
    extern __shared__ __align__(16) char dsm[];
    const uint32_t sbase = smem_u32(dsm);

    const int tid = threadIdx.x;
    const int wid = tid >> 5, lane = tid & 31;
    const int srow = tid >> 1, shalf = tid & 1;
    const uint32_t rowoff = (uint32_t)(srow * ROWB + shalf * 32);

    const float* Ap = A + ((size_t)blockIdx.y * 128 + srow) * (size_t)K + shalf * 16;
    const float* Bp = BT + ((size_t)blockIdx.x * 128 + srow) * (size_t)K + shalf * 16;

    float acc[4][4][4];
#pragma unroll
    for (int i = 0; i < 4; i++)
#pragma unroll
        for (int j = 0; j < 4; j++)
#pragma unroll
            for (int f = 0; f < 4; f++) acc[i][j][f] = 0.0f;

    float ra[16], rb[16];

#define LDG16(dst, ptr)                                          \
    {                                                            \
        *(float4*)((dst) + 0)  = *(const float4*)((ptr) + 0);    \
        *(float4*)((dst) + 4)  = *(const float4*)((ptr) + 4);    \
        *(float4*)((dst) + 8)  = *(const float4*)((ptr) + 8);    \
        *(float4*)((dst) + 12) = *(const float4*)((ptr) + 12);   \
    }

#define CVT_STS(hibase, lobase, r)                                               \
    {                                                                            \
        uint32_t hw[8], lw[8];                                                   \
        _Pragma("unroll") for (int i = 0; i < 8; i++) {                          \
            float f0 = (r)[2 * i], f1 = (r)[2 * i + 1];                          \
            __nv_bfloat16 h0 = __float2bfloat16_rn(f0);                          \
            __nv_bfloat16 h1 = __float2bfloat16_rn(f1);                          \
            __nv_bfloat16 l0 = __float2bfloat16_rn(f0 - __bfloat162float(h0));   \
            __nv_bfloat16 l1 = __float2bfloat16_rn(f1 - __bfloat162float(h1));   \
            hw[i] = ((uint32_t)__bfloat16_as_ushort(h1) << 16) |                 \
                    __bfloat16_as_ushort(h0);                                    \
            lw[i] = ((uint32_t)__bfloat16_as_ushort(l1) << 16) |                 \
                    __bfloat16_as_ushort(l0);                                    \
        }                                                                        \
        asm volatile("st.shared.v4.b32 [%0], {%1,%2,%3,%4};" ::"r"(hibase),      \
                     "r"(hw[0]), "r"(hw[1]), "r"(hw[2]), "r"(hw[3]) : "memory"); \
        asm volatile("st.shared.v4.b32 [%0], {%1,%2,%3,%4};" ::"r"(hibase + 16), \
                     "r"(hw[4]), "r"(hw[5]), "r"(hw[6]), "r"(hw[7]) : "memory"); \
        asm volatile("st.shared.v4.b32 [%0], {%1,%2,%3,%4};" ::"r"(lobase),      \
                     "r"(lw[0]), "r"(lw[1]), "r"(lw[2]), "r"(lw[3]) : "memory"); \
        asm volatile("st.shared.v4.b32 [%0], {%1,%2,%3,%4};" ::"r"(lobase + 16), \
                     "r"(lw[4]), "r"(lw[5]), "r"(lw[6]), "r"(lw[7]) : "memory"); \
    }

    const int CH = K >> 5;

    // prologue: stage chunk 0
    LDG16(ra, Ap);
    LDG16(rb, Bp);
    {
        uint32_t b0 = sbase + rowoff;
        CVT_STS(b0, b0 + PART, ra);
        uint32_t b2 = b0 + 2 * PART;
        CVT_STS(b2, b2 + PART, rb);
    }
    __syncthreads();

    const int m_base = (wid & 1) * 64;
    const int n_base = (wid >> 1) * 32;
    const int lgrp = lane >> 3, lr = lane & 7;

    for (int c = 0; c < CH; c++) {
        if (c + 1 < CH) {
            LDG16(ra, Ap + (size_t)(c + 1) * 32);
            LDG16(rb, Bp + (size_t)(c + 1) * 32);
        }
        const uint32_t sb0 = sbase + (uint32_t)(c & 1) * BUFB;
#pragma unroll
        for (int ks = 0; ks < 2; ks++) {
            uint32_t bh[4][2], bl[4][2];
#pragma unroll
            for (int p = 0; p < 2; p++) {
                uint32_t row = (uint32_t)(n_base + p * 16 + (lgrp >> 1) * 8 + lr);
                uint32_t ad = sb0 + 2 * PART + row * ROWB + ks * 32 + (lgrp & 1) * 16;
                uint32_t t[4];
                ldsm4(t, ad);
                bh[2 * p][0] = t[0]; bh[2 * p][1] = t[1];
                bh[2 * p + 1][0] = t[2]; bh[2 * p + 1][1] = t[3];
                ldsm4(t, ad + PART);
                bl[2 * p][0] = t[0]; bl[2 * p][1] = t[1];
                bl[2 * p + 1][0] = t[2]; bl[2 * p + 1][1] = t[3];
            }
#pragma unroll
            for (int mt = 0; mt < 4; mt++) {
                uint32_t row = (uint32_t)(m_base + mt * 16 + (lgrp & 1) * 8 + lr);
                uint32_t ad = sb0 + row * ROWB + ks * 32 + (lgrp >> 1) * 16;
                uint32_t ah[4], al[4];
                ldsm4(ah, ad);
                ldsm4(al, ad + PART);
#pragma unroll
                for (int nt = 0; nt < 4; nt++) {
                    mma_bf16(acc[mt][nt], ah, bh[nt]);
                    mma_bf16(acc[mt][nt], ah, bl[nt]);
                    mma_bf16(acc[mt][nt], al, bh[nt]);
                }
            }
        }
        if (c + 1 < CH) {
            uint32_t b0 = sbase + (uint32_t)((c + 1) & 1) * BUFB + rowoff;
            CVT_STS(b0, b0 + PART, ra);
            uint32_t b2 = b0 + 2 * PART;
            CVT_STS(b2, b2 + PART, rb);
        }
        __syncthreads();
    }

    // epilogue
    const int m0 = blockIdx.y * 128 + m_base;
    const int n0 = blockIdx.x * 128 + n_base;
    const int mr = lane >> 2, nc = (lane & 3) * 2;
#pragma unroll
    for (int mt = 0; mt < 4; mt++) {
#pragma unroll
        for (int half = 0; half < 2; half++) {
            const size_t m = (size_t)(m0 + mt * 16 + mr + half * 8);
#pragma unroll
            for (int nt = 0; nt < 4; nt++) {
                const int n = n0 + nt * 8 + nc;
                float v0 = acc[mt][nt][2 * half] * alpha;
                float v1 = acc[mt][nt][2 * half + 1] * alpha;
                if (BIAS) { v0 += bias[n]; v1 += bias[n + 1]; }
                if (RELU) { v0 = fmaxf(v0, 0.0f); v1 = fmaxf(v1, 0.0f); }
                if (RESID) {
                    float2 r2 = *(const float2*)(resid + m * N + n);
                    v0 += r2.x; v1 += r2.y;
                }
                float2 o; o.x = v0; o.y = v1;
                *(float2*)(C + m * N + n) = o;
            }
        }
    }
}

// ---------------------------------------------------------------------------
// Weight transpose: in [R,C] -> out [C,R], batched over blockIdx.z
// ---------------------------------------------------------------------------
__global__ void transpose_kernel(const float* __restrict__ in,
                                 float* __restrict__ out, int R, int C) {
    __shared__ float t[32][33];
    const size_t boff = (size_t)blockIdx.z * R * C;
    const int c0 = blockIdx.x * 32, r0 = blockIdx.y * 32;
    for (int k = threadIdx.y; k < 32; k += 8)
        t[k][threadIdx.x] = in[boff + (size_t)(r0 + k) * C + c0 + threadIdx.x];
    __syncthreads();
    for (int k = threadIdx.y; k < 32; k += 8)
        out[boff + (size_t)(c0 + k) * R + r0 + threadIdx.x] = t[threadIdx.x][k];
}

// ---------------------------------------------------------------------------
// Embedding + sinusoidal positional encoding
// ---------------------------------------------------------------------------
__global__ void embed_kernel(const int* __restrict__ inputs,
                             const float* __restrict__ emb) {
    int idx = blockIdx.x * blockDim.x + threadIdx.x;
    int s = idx >> 10;
    int d = idx & 1023;
    int tok = inputs[s];
    float val = emb[tok * DM + d];
    int k2 = d >> 1;
    float div = expf((float)(2 * k2) * (-9.210340371976184f / 1024.0f));
    float ang = (float)s * div;
    val += (d & 1) ? cosf(ang) : sinf(ang);
    g_x[idx] = val;
}

// ---------------------------------------------------------------------------
// LayerNorm
// ---------------------------------------------------------------------------
__device__ __forceinline__ float block_reduce_sum(float v) {
    __shared__ float sm[8];
    int lane = threadIdx.x & 31;
    int warp = threadIdx.x >> 5;
#pragma unroll
    for (int o = 16; o; o >>= 1) v += __shfl_xor_sync(0xffffffffu, v, o);
    if (lane == 0) sm[warp] = v;
    __syncthreads();
    if (warp == 0) {
        v = (lane < 8) ? sm[lane] : 0.0f;
#pragma unroll
        for (int o = 4; o; o >>= 1) v += __shfl_xor_sync(0xffffffffu, v, o);
        if (lane == 0) sm[0] = v;
    }
    __syncthreads();
    float r = sm[0];
    __syncthreads();
    return r;
}

__global__ void ln_kernel(const float* __restrict__ in,
                          const float* __restrict__ scale,
                          const float* __restrict__ bias,
                          float* __restrict__ out) {
    int row = blockIdx.x;
    float4 v = ((const float4*)(in + row * DM))[threadIdx.x];
    float mu = block_reduce_sum(v.x + v.y + v.z + v.w) * (1.0f / DM);
    float dx = v.x - mu, dy = v.y - mu, dz = v.z - mu, dw = v.w - mu;
    float var = block_reduce_sum(dx * dx + dy * dy + dz * dz + dw * dw) * (1.0f / DM);
    float rs = rsqrtf(var + 1e-6f);
    float4 s4 = ((const float4*)scale)[threadIdx.x];
    float4 b4 = ((const float4*)bias)[threadIdx.x];
    float4 o;
    o.x = dx * rs * s4.x + b4.x;
    o.y = dy * rs * s4.y + b4.y;
    o.z = dz * rs * s4.z + b4.z;
    o.w = dw * rs * s4.w + b4.w;
    ((float4*)(out + row * DM))[threadIdx.x] = o;
}

// ---------------------------------------------------------------------------
// Sparse attention (band + global), one block per (query, head)
// ---------------------------------------------------------------------------
__global__ __launch_bounds__(128) void attn_kernel() {
    int i = blockIdx.x;
    int head = blockIdx.y;
    __shared__ float qs[HDIM];
    __shared__ float sc[SQ];
    __shared__ float red[128];
    int tid = threadIdx.x;

    if (tid < HDIM) qs[tid] = g_q[(size_t)i * DM + head * HDIM + tid];
    __syncthreads();

    int n0, r1lo, r1hi;
    if (i < NG) {
        n0 = SQ; r1lo = 0; r1hi = 0;
    } else {
        n0 = NG;
        r1lo = max(NG, i - HALFW);
        r1hi = min(SQ, i + HALFW + 1);
    }
    int n = n0 + (r1hi - r1lo);

    int warp = tid >> 5, lane = tid & 31;
    for (int t = warp; t < n; t += 4) {
        int j = (t < n0) ? t : (r1lo + (t - n0));
        const float* kr = g_k + (size_t)j * DM + head * HDIM;
        float2 kk = ((const float2*)kr)[lane];
        float p = qs[2 * lane] * kk.x + qs[2 * lane + 1] * kk.y;
#pragma unroll
        for (int o = 16; o; o >>= 1) p += __shfl_xor_sync(0xffffffffu, p, o);
        if (lane == 0) sc[t] = p;
    }
    __syncthreads();

    float mx = -1e30f;
    for (int t = tid; t < n; t += 128) mx = fmaxf(mx, sc[t]);
    red[tid] = mx;
    __syncthreads();
    for (int s2 = 64; s2 > 0; s2 >>= 1) {
        if (tid < s2) red[tid] = fmaxf(red[tid], red[tid + s2]);
        __syncthreads();
    }
    mx = red[0];
    __syncthreads();

    float lsum = 0.0f;
    for (int t = tid; t < n; t += 128) {
        float e = expf(sc[t] - mx);
        sc[t] = e;
        lsum += e;
    }
    red[tid] = lsum;
    __syncthreads();
    for (int s2 = 64; s2 > 0; s2 >>= 1) {
        if (tid < s2) red[tid] += red[tid + s2];
        __syncthreads();
    }
    float denom = red[0];
    __syncthreads();

    int g = tid >> 6;
    int d = tid & 63;
    float acc = 0.0f;
    for (int t = g; t < n; t += 2) {
        int j = (t < n0) ? t : (r1lo + (t - n0));
        acc += sc[t] * g_v[(size_t)j * DM + head * HDIM + d];
    }
    red[tid] = acc;
    __syncthreads();
    if (tid < 64)
        g_ctx[(size_t)i * DM + head * HDIM + tid] = (red[tid] + red[64 + tid]) / denom;
}

// ---------------------------------------------------------------------------
// Launch
// ---------------------------------------------------------------------------
extern "C" void kernel_launch(void* const* d_in, const int* in_sizes, int n_in,
                              void* d_out, int out_size) {
    const int* inputs = (const int*)d_in[0];
    const float* embed = (const float*)d_in[2];
    const float* wq = (const float*)d_in[3];
    const float* wk = (const float*)d_in[4];
    const float* wv = (const float*)d_in[5];
    const float* wo = (const float*)d_in[6];
    const float* ln1s = (const float*)d_in[7];
    const float* ln1b = (const float*)d_in[8];
    const float* ln2s = (const float*)d_in[9];
    const float* ln2b = (const float*)d_in[10];
    const float* w1 = (const float*)d_in[11];
    const float* b1 = (const float*)d_in[12];
    const float* w2 = (const float*)d_in[13];
    const float* b2 = (const float*)d_in[14];
    const float* lnfs = (const float*)d_in[15];
    const float* lnfb = (const float*)d_in[16];
    float* out = (float*)d_out;

    float *xp, *hp, *qp, *kp, *vp, *cp, *yp;
    float *wqT, *wkT, *wvT, *woT, *w1T, *w2T;
    cudaGetSymbolAddress((void**)&xp, g_x);
    cudaGetSymbolAddress((void**)&hp, g_h);
    cudaGetSymbolAddress((void**)&qp, g_q);
    cudaGetSymbolAddress((void**)&kp, g_k);
    cudaGetSymbolAddress((void**)&vp, g_v);
    cudaGetSymbolAddress((void**)&cp, g_ctx);
    cudaGetSymbolAddress((void**)&yp, g_y1);
    cudaGetSymbolAddress((void**)&wqT, g_wqT);
    cudaGetSymbolAddress((void**)&wkT, g_wkT);
    cudaGetSymbolAddress((void**)&wvT, g_wvT);
    cudaGetSymbolAddress((void**)&woT, g_woT);
    cudaGetSymbolAddress((void**)&w1T, g_w1T);
    cudaGetSymbolAddress((void**)&w2T, g_w2T);

    cudaFuncSetAttribute(mma_gemm<0, 0, 0>, cudaFuncAttributeMaxDynamicSharedMemorySize, DYNSM);
    cudaFuncSetAttribute(mma_gemm<0, 0, 1>, cudaFuncAttributeMaxDynamicSharedMemorySize, DYNSM);
    cudaFuncSetAttribute(mma_gemm<1, 1, 0>, cudaFuncAttributeMaxDynamicSharedMemorySize, DYNSM);
    cudaFuncSetAttribute(mma_gemm<1, 0, 1>, cudaFuncAttributeMaxDynamicSharedMemorySize, DYNSM);

    dim3 tb(32, 8);
    transpose_kernel<<<dim3(32, 32, NL), tb>>>(wq, wqT, DM, DM);
    transpose_kernel<<<dim3(32, 32, NL), tb>>>(wk, wkT, DM, DM);
    transpose_kernel<<<dim3(32, 32, NL), tb>>>(wv, wvT, DM, DM);
    transpose_kernel<<<dim3(32, 32, NL), tb>>>(wo, woT, DM, DM);
    transpose_kernel<<<dim3(MLPD / 32, DM / 32, NL), tb>>>(w1, w1T, DM, MLPD);
    transpose_kernel<<<dim3(DM / 32, MLPD / 32, NL), tb>>>(w2, w2T, MLPD, DM);

    embed_kernel<<<SQ * DM / 256, 256>>>(inputs, embed);

    const size_t W_ATT = (size_t)DM * DM;
    const size_t W_MLP = (size_t)DM * MLPD;
    dim3 g_1024(DM / 128, SQ / 128);
    dim3 g_4096(MLPD / 128, SQ / 128);

    for (int l = 0; l < NL; l++) {
        ln_kernel<<<SQ, 256>>>(xp, ln1s + l * DM, ln1b + l * DM, hp);

        mma_gemm<0, 0, 0><<<g_1024, 256, DYNSM>>>(hp, wqT + l * W_ATT, nullptr, nullptr,
                                                  qp, DM, DM, 0.125f);
        mma_gemm<0, 0, 0><<<g_1024, 256, DYNSM>>>(hp, wkT + l * W_ATT, nullptr, nullptr,
                                                  kp, DM, DM, 1.0f);
        mma_gemm<0, 0, 0><<<g_1024, 256, DYNSM>>>(hp, wvT + l * W_ATT, nullptr, nullptr,
                                                  vp, DM, DM, 1.0f);

        attn_kernel<<<dim3(SQ, NH), 128>>>();

        mma_gemm<0, 0, 1><<<g_1024, 256, DYNSM>>>(cp, woT + l * W_ATT, nullptr, xp,
                                                  xp, DM, DM, 1.0f);

        ln_kernel<<<SQ, 256>>>(xp, ln2s + l * DM, ln2b + l * DM, hp);

        mma_gemm<1, 1, 0><<<g_4096, 256, DYNSM>>>(hp, w1T + l * W_MLP, b1 + l * MLPD,
                                                  nullptr, yp, DM, MLPD, 1.0f);
        mma_gemm<1, 0, 1><<<g_1024, 256, DYNSM>>>(yp, w2T + l * W_MLP, b2 + l * DM, xp,
                                                  xp, MLPD, DM, 1.0f);
    }

    ln_kernel<<<SQ, 256>>>(xp, lnfs, lnfb, out);
}